// round 1
// baseline (speedup 1.0000x reference)
#include <cuda_runtime.h>

#define NN 50000
#define EE 800000
#define FD 128
#define NC 64

// ---------------- scratch (static device globals; no allocation) ----------------
__device__ int   g_cnt[NN];
__device__ int   g_rowptr[NN + 1];
__device__ int   g_cursor[NN];
__device__ int   g_srcs[EE];
__device__ float g_t[NN * FD];   // gather operand (h @ Wn), layer2: [h2@Wn2 | noise@Wn2]
__device__ float g_s[NN * FD];   // self term (h @ Ws + b), layer2: [h2@Ws2+b2 | noise@Ws2]
__device__ float g_h[NN * FD];   // current hidden state

// ---------------- CSR build ----------------
__global__ void k_zero_cnt() {
    int i = blockIdx.x * blockDim.x + threadIdx.x;
    if (i < NN) g_cnt[i] = 0;
}

__global__ void k_count(const int* __restrict__ dst) {
    int i = blockIdx.x * blockDim.x + threadIdx.x;
    if (i < EE) atomicAdd(&g_cnt[dst[i]], 1);
}

// single-block exclusive scan of g_cnt -> g_rowptr (and cursor copy)
__global__ void k_scan() {
    __shared__ int sums[1024];
    const int t = threadIdx.x;
    const int CH = (NN + 1023) / 1024;  // 49
    int lo = t * CH;
    int hi = lo + CH; if (hi > NN) hi = NN;
    int s = 0;
    for (int i = lo; i < hi; i++) s += g_cnt[i];
    sums[t] = s;
    __syncthreads();
    // Hillis-Steele inclusive scan
    for (int off = 1; off < 1024; off <<= 1) {
        int v = (t >= off) ? sums[t - off] : 0;
        __syncthreads();
        sums[t] += v;
        __syncthreads();
    }
    int base = (t == 0) ? 0 : sums[t - 1];
    for (int i = lo; i < hi; i++) {
        g_rowptr[i] = base;
        g_cursor[i] = base;
        base += g_cnt[i];
    }
    if (t == 1023) g_rowptr[NN] = EE;
}

__global__ void k_scatter(const int* __restrict__ src, const int* __restrict__ dst) {
    int i = blockIdx.x * blockDim.x + threadIdx.x;
    if (i < EE) {
        int p = atomicAdd(&g_cursor[dst[i]], 1);
        g_srcs[p] = src[i];
    }
}

// ---------------- GEMM: D[:, col_off:col_off+FO] = A[N,128] @ W[128,FO] (+bias) ----------------
// Block tile: 128 rows x FO cols, 128 threads. Micro-tile 8 x TN per thread.
template <int FO>
__global__ void k_gemm(const float* __restrict__ A, const float* __restrict__ W,
                       const float* __restrict__ bias, float* __restrict__ D,
                       int col_off) {
    constexpr int TN = (FO == 128) ? 16 : 8;
    constexpr int TX = FO / TN;  // 8
    __shared__ float As[16][132];
    __shared__ float Wsh[16][FO + 4];

    const int tid = threadIdx.x;
    const int tx = tid % TX;
    const int ty = tid / TX;        // 0..15
    const int m0 = blockIdx.x * 128;
    const int r0 = ty * 8;
    const int c0 = tx * TN;

    float acc[8][TN];
#pragma unroll
    for (int i = 0; i < 8; i++)
#pragma unroll
        for (int j = 0; j < TN; j++) acc[i][j] = 0.0f;

    for (int k0 = 0; k0 < 128; k0 += 16) {
        // stage A chunk (transposed to k-major)
#pragma unroll
        for (int i = tid; i < 512; i += 128) {
            int m = i >> 2, g = i & 3;
            int row = m0 + m;
            float4 v = make_float4(0.f, 0.f, 0.f, 0.f);
            if (row < NN) v = *(const float4*)&A[row * 128 + k0 + g * 4];
            As[g * 4 + 0][m] = v.x;
            As[g * 4 + 1][m] = v.y;
            As[g * 4 + 2][m] = v.z;
            As[g * 4 + 3][m] = v.w;
        }
        // stage W chunk
#pragma unroll
        for (int i = tid; i < 16 * FO / 4; i += 128) {
            int kk = i / (FO / 4);
            int c = (i % (FO / 4)) * 4;
            *(float4*)&Wsh[kk][c] = *(const float4*)&W[(k0 + kk) * FO + c];
        }
        __syncthreads();
#pragma unroll
        for (int kk = 0; kk < 16; kk++) {
            float a[8], w[TN];
#pragma unroll
            for (int i = 0; i < 8; i += 4) {
                float4 v = *(const float4*)&As[kk][r0 + i];
                a[i] = v.x; a[i + 1] = v.y; a[i + 2] = v.z; a[i + 3] = v.w;
            }
#pragma unroll
            for (int j = 0; j < TN; j += 4) {
                float4 v = *(const float4*)&Wsh[kk][c0 + j];
                w[j] = v.x; w[j + 1] = v.y; w[j + 2] = v.z; w[j + 3] = v.w;
            }
#pragma unroll
            for (int i = 0; i < 8; i++)
#pragma unroll
                for (int j = 0; j < TN; j++) acc[i][j] = fmaf(a[i], w[j], acc[i][j]);
        }
        __syncthreads();
    }

    float bv[TN];
#pragma unroll
    for (int j = 0; j < TN; j++) bv[j] = bias ? bias[c0 + j] : 0.0f;

#pragma unroll
    for (int i = 0; i < 8; i++) {
        int row = m0 + r0 + i;
        if (row < NN) {
#pragma unroll
            for (int j = 0; j < TN; j += 4) {
                float4 v;
                v.x = acc[i][j + 0] + bv[j + 0];
                v.y = acc[i][j + 1] + bv[j + 1];
                v.z = acc[i][j + 2] + bv[j + 2];
                v.w = acc[i][j + 3] + bv[j + 3];
                *(float4*)&D[row * 128 + col_off + c0 + j] = v;
            }
        }
    }
}

// ---------------- aggregation (warp per node) ----------------
// mode 0: out = relu(s + deg_inv * segsum(t[src]))
// mode 1: v = s + deg_inv*agg ; out[:, 0:64] = v[:,0:64] + v[:,64:128]; out[:, 64:128] = v[:,0:64]
__global__ void k_agg(const float* __restrict__ t, const float* __restrict__ s,
                      float* __restrict__ out, int mode) {
    int warp = (blockIdx.x * blockDim.x + threadIdx.x) >> 5;
    int lane = threadIdx.x & 31;
    if (warp >= NN) return;
    int b = g_rowptr[warp];
    int e = g_rowptr[warp + 1];
    int deg = e - b;
    float dinv = 1.0f / (float)(deg > 1 ? deg : 1);

    float4 a0 = make_float4(0.f, 0.f, 0.f, 0.f);
    float4 a1 = make_float4(0.f, 0.f, 0.f, 0.f);
    int i = b;
    for (; i + 1 < e; i += 2) {
        int s0 = g_srcs[i];
        int s1 = g_srcs[i + 1];
        float4 v0 = *(const float4*)&t[s0 * 128 + lane * 4];
        float4 v1 = *(const float4*)&t[s1 * 128 + lane * 4];
        a0.x += v0.x; a0.y += v0.y; a0.z += v0.z; a0.w += v0.w;
        a1.x += v1.x; a1.y += v1.y; a1.z += v1.z; a1.w += v1.w;
    }
    if (i < e) {
        int s0 = g_srcs[i];
        float4 v0 = *(const float4*)&t[s0 * 128 + lane * 4];
        a0.x += v0.x; a0.y += v0.y; a0.z += v0.z; a0.w += v0.w;
    }
    float4 sv = *(const float4*)&s[warp * 128 + lane * 4];
    float4 r;
    r.x = fmaf(a0.x + a1.x, dinv, sv.x);
    r.y = fmaf(a0.y + a1.y, dinv, sv.y);
    r.z = fmaf(a0.z + a1.z, dinv, sv.z);
    r.w = fmaf(a0.w + a1.w, dinv, sv.w);

    if (mode == 0) {
        r.x = fmaxf(r.x, 0.f); r.y = fmaxf(r.y, 0.f);
        r.z = fmaxf(r.z, 0.f); r.w = fmaxf(r.w, 0.f);
        *(float4*)&out[warp * 128 + lane * 4] = r;
    } else {
        float4 o;
        o.x = __shfl_xor_sync(0xffffffffu, r.x, 16);
        o.y = __shfl_xor_sync(0xffffffffu, r.y, 16);
        o.z = __shfl_xor_sync(0xffffffffu, r.z, 16);
        o.w = __shfl_xor_sync(0xffffffffu, r.w, 16);
        float4 res;
        if (lane < 16) {  // cols 0..63: h_noise = h3 + delta
            res.x = r.x + o.x; res.y = r.y + o.y; res.z = r.z + o.z; res.w = r.w + o.w;
        } else {          // cols 64..127: h3 (value from partner lane)
            res = o;
        }
        *(float4*)&out[warp * 128 + lane * 4] = res;
    }
}

// ---------------- launch ----------------
extern "C" void kernel_launch(void* const* d_in, const int* in_sizes, int n_in,
                              void* d_out, int out_size) {
    const float* features = (const float*)d_in[0];
    const float* noise    = (const float*)d_in[1];
    const float* Ws0 = (const float*)d_in[2];
    const float* Wn0 = (const float*)d_in[3];
    const float* b0  = (const float*)d_in[4];
    const float* Ws1 = (const float*)d_in[5];
    const float* Wn1 = (const float*)d_in[6];
    const float* b1  = (const float*)d_in[7];
    const float* Ws2 = (const float*)d_in[8];
    const float* Wn2 = (const float*)d_in[9];
    const float* b2  = (const float*)d_in[10];
    const int* edge_src = (const int*)d_in[11];
    const int* edge_dst = (const int*)d_in[12];
    float* out = (float*)d_out;

    float* t_p; cudaGetSymbolAddress((void**)&t_p, g_t);
    float* s_p; cudaGetSymbolAddress((void**)&s_p, g_s);
    float* h_p; cudaGetSymbolAddress((void**)&h_p, g_h);

    const int GB = (NN + 127) / 128;        // gemm blocks: 391
    const int AB = (NN * 32 + 255) / 256;   // agg blocks: 6250

    // CSR build
    k_zero_cnt<<<(NN + 255) / 256, 256>>>();
    k_count<<<(EE + 255) / 256, 256>>>(edge_dst);
    k_scan<<<1, 1024>>>();
    k_scatter<<<(EE + 255) / 256, 256>>>(edge_src, edge_dst);

    // layer 0
    k_gemm<128><<<GB, 128>>>(features, Wn0, nullptr, t_p, 0);
    k_gemm<128><<<GB, 128>>>(features, Ws0, b0, s_p, 0);
    k_agg<<<AB, 256>>>(t_p, s_p, h_p, 0);

    // layer 1
    k_gemm<128><<<GB, 128>>>(h_p, Wn1, nullptr, t_p, 0);
    k_gemm<128><<<GB, 128>>>(h_p, Ws1, b1, s_p, 0);
    k_agg<<<AB, 256>>>(t_p, s_p, h_p, 0);

    // layer 2 (linear): t = [h2@Wn2 | noise@Wn2], s = [h2@Ws2+b2 | noise@Ws2]
    k_gemm<64><<<GB, 128>>>(h_p,   Wn2, nullptr, t_p, 0);
    k_gemm<64><<<GB, 128>>>(noise, Wn2, nullptr, t_p, 64);
    k_gemm<64><<<GB, 128>>>(h_p,   Ws2, b2,      s_p, 0);
    k_gemm<64><<<GB, 128>>>(noise, Ws2, nullptr, s_p, 64);
    k_agg<<<AB, 256>>>(t_p, s_p, out, 1);
}

// round 3
// speedup vs baseline: 1.9845x; 1.9845x over previous
#include <cuda_runtime.h>
#include <cuda_bf16.h>
#include <cstdint>

#define NN 50000
#define EE 800000

// ---------------- scratch (static device globals; no allocation) ----------------
__device__ int   g_cnt[NN];
__device__ int   g_rowptr[NN + 1];
__device__ int   g_cursor[NN];
__device__ int   g_srcs[EE];
__device__ float g_t[NN * 128];   // gather operand (h @ Wn); layer2: [h2@Wn2 | noise@Wn2]
__device__ float g_s[NN * 128];   // self term (h @ Ws + b); layer2: [h2@Ws2+b2 | noise@Ws2]
__device__ float g_h[NN * 128];   // current hidden state
// pre-split transposed weights: Wt[f][k] = W[k][f], bf16 hi/lo. m: 0=Wn0 1=Ws0 2=Wn1 3=Ws1 4=Wn2 5=Ws2
__device__ __nv_bfloat16 g_wt_hi[6][128 * 128];
__device__ __nv_bfloat16 g_wt_lo[6][128 * 128];

// ---------------- CSR build ----------------
__global__ void k_zero_cnt() {
    int i = blockIdx.x * blockDim.x + threadIdx.x;
    if (i < NN) g_cnt[i] = 0;
}
__global__ void k_count(const int* __restrict__ dst) {
    int i = blockIdx.x * blockDim.x + threadIdx.x;
    if (i < EE) atomicAdd(&g_cnt[dst[i]], 1);
}
__global__ void k_scan() {
    __shared__ int sums[1024];
    const int t = threadIdx.x;
    const int CH = (NN + 1023) / 1024;
    int lo = t * CH;
    int hi = lo + CH; if (hi > NN) hi = NN;
    int s = 0;
    for (int i = lo; i < hi; i++) s += g_cnt[i];
    sums[t] = s;
    __syncthreads();
    for (int off = 1; off < 1024; off <<= 1) {
        int v = (t >= off) ? sums[t - off] : 0;
        __syncthreads();
        sums[t] += v;
        __syncthreads();
    }
    int base = (t == 0) ? 0 : sums[t - 1];
    for (int i = lo; i < hi; i++) {
        g_rowptr[i] = base;
        g_cursor[i] = base;
        base += g_cnt[i];
    }
    if (t == 1023) g_rowptr[NN] = EE;
}
__global__ void k_scatter(const int* __restrict__ src, const int* __restrict__ dst) {
    int i = blockIdx.x * blockDim.x + threadIdx.x;
    if (i < EE) {
        int p = atomicAdd(&g_cursor[dst[i]], 1);
        g_srcs[p] = src[i];
    }
}

// ---------------- weight prep: transpose + bf16 hi/lo split ----------------
__global__ void k_prep_w(const float* Wn0, const float* Ws0, const float* Wn1,
                         const float* Ws1, const float* Wn2, const float* Ws2) {
    int m = blockIdx.y;
    int f = blockIdx.x;
    int k = threadIdx.x;
    const float* W; int FO;
    switch (m) {
        case 0: W = Wn0; FO = 128; break;
        case 1: W = Ws0; FO = 128; break;
        case 2: W = Wn1; FO = 128; break;
        case 3: W = Ws1; FO = 128; break;
        case 4: W = Wn2; FO = 64; break;
        default: W = Ws2; FO = 64; break;
    }
    if (f >= FO) return;
    float x = W[k * FO + f];
    __nv_bfloat16 h = __float2bfloat16(x);
    float r = x - __bfloat162float(h);
    g_wt_hi[m][f * 128 + k] = h;
    g_wt_lo[m][f * 128 + k] = __float2bfloat16(r);
}

// ---------------- mma.sync bf16 helper ----------------
__device__ __forceinline__ void mma_bf16(float* c, uint32_t a0, uint32_t a1,
                                         uint32_t a2, uint32_t a3,
                                         uint32_t b0, uint32_t b1) {
    asm volatile(
        "mma.sync.aligned.m16n8k16.row.col.f32.bf16.bf16.f32 "
        "{%0,%1,%2,%3}, {%4,%5,%6,%7}, {%8,%9}, {%0,%1,%2,%3};"
        : "+f"(c[0]), "+f"(c[1]), "+f"(c[2]), "+f"(c[3])
        : "r"(a0), "r"(a1), "r"(a2), "r"(a3), "r"(b0), "r"(b1));
}

// ---------------- fused GEMM: t = A@Wn, s = A@Ws (+bias) via mma.sync ----------------
// A: [NN,128] fp32. CTA: 128 rows x FO cols, 256 threads (8 warps, 16 rows each).
// 3-term bf16 split: AhiWhi + AloWhi + AhiWlo, fp32 accumulate.
#define SA 136   // smem row stride in bf16 elems (conflict-free for fragment loads)
template <int FO>
__global__ void __launch_bounds__(256) k_mma_gemm(
    const float* __restrict__ A,
    const __nv_bfloat16* __restrict__ wnh, const __nv_bfloat16* __restrict__ wnl,
    const __nv_bfloat16* __restrict__ wsh, const __nv_bfloat16* __restrict__ wsl,
    const float* __restrict__ bias,
    float* __restrict__ t_out, float* __restrict__ s_out, int col_off) {
    extern __shared__ __nv_bfloat16 sm[];
    __nv_bfloat16* Ahi = sm;                       // 128 x SA
    __nv_bfloat16* Alo = sm + 128 * SA;
    __nv_bfloat16* Wb  = sm + 2 * 128 * SA;        // 4 tiles of FO x SA: WnHi WnLo WsHi WsLo
    constexpr int WT = FO * SA;
    constexpr int NT = FO / 8;

    const int tid = threadIdx.x;
    const int wid = tid >> 5;
    const int lane = tid & 31;
    const int gid = lane >> 2;
    const int tig = lane & 3;
    const int m0 = blockIdx.x * 128;

    // ---- stage A: fp32 -> bf16 hi/lo ----
    {
        const float4* Ap = (const float4*)A;
#pragma unroll
        for (int it = 0; it < 16; it++) {
            int idx = it * 256 + tid;       // 4096 float4 chunks
            int r = idx >> 5;
            int c4 = idx & 31;
            int row = m0 + r;
            float4 v = make_float4(0.f, 0.f, 0.f, 0.f);
            if (row < NN) v = Ap[row * 32 + c4];
            unsigned short hb[4], lb[4];
            float xv[4] = {v.x, v.y, v.z, v.w};
#pragma unroll
            for (int j = 0; j < 4; j++) {
                __nv_bfloat16 h = __float2bfloat16(xv[j]);
                float res = xv[j] - __bfloat162float(h);
                hb[j] = __bfloat16_as_ushort(h);
                lb[j] = __bfloat16_as_ushort(__float2bfloat16(res));
            }
            unsigned long long hv = (unsigned long long)hb[0] | ((unsigned long long)hb[1] << 16) |
                                    ((unsigned long long)hb[2] << 32) | ((unsigned long long)hb[3] << 48);
            unsigned long long lv = (unsigned long long)lb[0] | ((unsigned long long)lb[1] << 16) |
                                    ((unsigned long long)lb[2] << 32) | ((unsigned long long)lb[3] << 48);
            *(unsigned long long*)&Ahi[r * SA + c4 * 4] = hv;
            *(unsigned long long*)&Alo[r * SA + c4 * 4] = lv;
        }
    }
    // ---- stage W tiles (already transposed/split; copy with pad) ----
    {
        const __nv_bfloat16* wt[4] = {wnh, wnl, wsh, wsl};
#pragma unroll
        for (int j = 0; j < 4; j++) {
            const uint4* src = (const uint4*)wt[j];
            __nv_bfloat16* dst = Wb + j * WT;
            for (int c = tid; c < FO * 16; c += 256) {
                int f = c >> 4;
                int k8 = (c & 15) * 8;
                *(uint4*)&dst[f * SA + k8] = src[c];
            }
        }
    }
    __syncthreads();

    const int r0 = wid * 16;
    const int rowA = m0 + r0 + gid;
    const int rowB = rowA + 8;

#pragma unroll
    for (int out = 0; out < 2; out++) {
        const __nv_bfloat16* Bhi = Wb + (out * 2 + 0) * WT;
        const __nv_bfloat16* Blo = Wb + (out * 2 + 1) * WT;
        float acc[NT][4];
#pragma unroll
        for (int n = 0; n < NT; n++) {
            acc[n][0] = acc[n][1] = acc[n][2] = acc[n][3] = 0.f;
        }
#pragma unroll
        for (int ks = 0; ks < 8; ks++) {
            const int k0 = ks * 16;
            const int ka = k0 + tig * 2;
            uint32_t ah0 = *(const uint32_t*)&Ahi[(r0 + gid)     * SA + ka];
            uint32_t ah1 = *(const uint32_t*)&Ahi[(r0 + gid + 8) * SA + ka];
            uint32_t ah2 = *(const uint32_t*)&Ahi[(r0 + gid)     * SA + ka + 8];
            uint32_t ah3 = *(const uint32_t*)&Ahi[(r0 + gid + 8) * SA + ka + 8];
            uint32_t al0 = *(const uint32_t*)&Alo[(r0 + gid)     * SA + ka];
            uint32_t al1 = *(const uint32_t*)&Alo[(r0 + gid + 8) * SA + ka];
            uint32_t al2 = *(const uint32_t*)&Alo[(r0 + gid)     * SA + ka + 8];
            uint32_t al3 = *(const uint32_t*)&Alo[(r0 + gid + 8) * SA + ka + 8];
#pragma unroll
            for (int nt = 0; nt < NT; nt++) {
                const int nr = nt * 8 + gid;
                uint32_t bh0 = *(const uint32_t*)&Bhi[nr * SA + ka];
                uint32_t bh1 = *(const uint32_t*)&Bhi[nr * SA + ka + 8];
                uint32_t bl0 = *(const uint32_t*)&Blo[nr * SA + ka];
                uint32_t bl1 = *(const uint32_t*)&Blo[nr * SA + ka + 8];
                mma_bf16(acc[nt], ah0, ah1, ah2, ah3, bh0, bh1);
                mma_bf16(acc[nt], al0, al1, al2, al3, bh0, bh1);
                mma_bf16(acc[nt], ah0, ah1, ah2, ah3, bl0, bl1);
            }
        }
        // ---- epilogue ----
        float* D = (out == 0) ? t_out : s_out;
#pragma unroll
        for (int nt = 0; nt < NT; nt++) {
            const int col = col_off + nt * 8 + tig * 2;
            float bx = 0.f, by = 0.f;
            if (out == 1 && bias) { bx = bias[nt * 8 + tig * 2]; by = bias[nt * 8 + tig * 2 + 1]; }
            if (rowA < NN) {
                float2 v = make_float2(acc[nt][0] + bx, acc[nt][1] + by);
                *(float2*)&D[rowA * 128 + col] = v;
            }
            if (rowB < NN) {
                float2 v = make_float2(acc[nt][2] + bx, acc[nt][3] + by);
                *(float2*)&D[rowB * 128 + col] = v;
            }
        }
    }
}

// ---------------- aggregation (warp per node) ----------------
__global__ void k_agg(const float* __restrict__ t, const float* __restrict__ s,
                      float* __restrict__ out, int mode) {
    int warp = (blockIdx.x * blockDim.x + threadIdx.x) >> 5;
    int lane = threadIdx.x & 31;
    if (warp >= NN) return;
    int b = g_rowptr[warp];
    int e = g_rowptr[warp + 1];
    int deg = e - b;
    float dinv = 1.0f / (float)(deg > 1 ? deg : 1);

    float4 a0 = make_float4(0.f, 0.f, 0.f, 0.f);
    float4 a1 = make_float4(0.f, 0.f, 0.f, 0.f);
    int i = b;
    for (; i + 1 < e; i += 2) {
        int s0 = g_srcs[i];
        int s1 = g_srcs[i + 1];
        float4 v0 = *(const float4*)&t[s0 * 128 + lane * 4];
        float4 v1 = *(const float4*)&t[s1 * 128 + lane * 4];
        a0.x += v0.x; a0.y += v0.y; a0.z += v0.z; a0.w += v0.w;
        a1.x += v1.x; a1.y += v1.y; a1.z += v1.z; a1.w += v1.w;
    }
    if (i < e) {
        int s0 = g_srcs[i];
        float4 v0 = *(const float4*)&t[s0 * 128 + lane * 4];
        a0.x += v0.x; a0.y += v0.y; a0.z += v0.z; a0.w += v0.w;
    }
    float4 sv = *(const float4*)&s[warp * 128 + lane * 4];
    float4 r;
    r.x = fmaf(a0.x + a1.x, dinv, sv.x);
    r.y = fmaf(a0.y + a1.y, dinv, sv.y);
    r.z = fmaf(a0.z + a1.z, dinv, sv.z);
    r.w = fmaf(a0.w + a1.w, dinv, sv.w);

    if (mode == 0) {
        r.x = fmaxf(r.x, 0.f); r.y = fmaxf(r.y, 0.f);
        r.z = fmaxf(r.z, 0.f); r.w = fmaxf(r.w, 0.f);
        *(float4*)&out[warp * 128 + lane * 4] = r;
    } else {
        float4 o;
        o.x = __shfl_xor_sync(0xffffffffu, r.x, 16);
        o.y = __shfl_xor_sync(0xffffffffu, r.y, 16);
        o.z = __shfl_xor_sync(0xffffffffu, r.z, 16);
        o.w = __shfl_xor_sync(0xffffffffu, r.w, 16);
        float4 res;
        if (lane < 16) {
            res.x = r.x + o.x; res.y = r.y + o.y; res.z = r.z + o.z; res.w = r.w + o.w;
        } else {
            res = o;
        }
        *(float4*)&out[warp * 128 + lane * 4] = res;
    }
}

// ---------------- launch ----------------
extern "C" void kernel_launch(void* const* d_in, const int* in_sizes, int n_in,
                              void* d_out, int out_size) {
    const float* features = (const float*)d_in[0];
    const float* noise    = (const float*)d_in[1];
    const float* Ws0 = (const float*)d_in[2];
    const float* Wn0 = (const float*)d_in[3];
    const float* b0  = (const float*)d_in[4];
    const float* Ws1 = (const float*)d_in[5];
    const float* Wn1 = (const float*)d_in[6];
    const float* b1  = (const float*)d_in[7];
    const float* Ws2 = (const float*)d_in[8];
    const float* Wn2 = (const float*)d_in[9];
    const float* b2  = (const float*)d_in[10];
    const int* edge_src = (const int*)d_in[11];
    const int* edge_dst = (const int*)d_in[12];
    float* out = (float*)d_out;

    float* t_p; cudaGetSymbolAddress((void**)&t_p, g_t);
    float* s_p; cudaGetSymbolAddress((void**)&s_p, g_s);
    float* h_p; cudaGetSymbolAddress((void**)&h_p, g_h);
    __nv_bfloat16* wh; cudaGetSymbolAddress((void**)&wh, g_wt_hi);
    __nv_bfloat16* wl; cudaGetSymbolAddress((void**)&wl, g_wt_lo);

    const int SM128 = (2 * 128 * SA + 4 * 128 * SA) * 2;   // 208896 B
    const int SM64  = (2 * 128 * SA + 4 * 64 * SA) * 2;    // 139264 B
    cudaFuncSetAttribute(k_mma_gemm<128>, cudaFuncAttributeMaxDynamicSharedMemorySize, SM128);
    cudaFuncSetAttribute(k_mma_gemm<64>,  cudaFuncAttributeMaxDynamicSharedMemorySize, SM64);

    const int GB = (NN + 127) / 128;        // 391
    const int AB = (NN * 32 + 255) / 256;   // 6250

    // CSR build + weight prep
    k_zero_cnt<<<(NN + 255) / 256, 256>>>();
    k_count<<<(EE + 255) / 256, 256>>>(edge_dst);
    k_scan<<<1, 1024>>>();
    k_scatter<<<(EE + 255) / 256, 256>>>(edge_src, edge_dst);
    k_prep_w<<<dim3(128, 6), 128>>>(Wn0, Ws0, Wn1, Ws1, Wn2, Ws2);

    // layer 0: t = X@Wn0, s = X@Ws0+b0 ; h = relu(s + dinv*agg(t))
    k_mma_gemm<128><<<GB, 256, SM128>>>(features, wh + 0 * 16384, wl + 0 * 16384,
                                        wh + 1 * 16384, wl + 1 * 16384, b0, t_p, s_p, 0);
    k_agg<<<AB, 256>>>(t_p, s_p, h_p, 0);

    // layer 1
    k_mma_gemm<128><<<GB, 256, SM128>>>(h_p, wh + 2 * 16384, wl + 2 * 16384,
                                        wh + 3 * 16384, wl + 3 * 16384, b1, t_p, s_p, 0);
    k_agg<<<AB, 256>>>(t_p, s_p, h_p, 0);

    // layer 2 (linear): cols 0:64 from h2, 64:128 from noise
    k_mma_gemm<64><<<GB, 256, SM64>>>(h_p, wh + 4 * 16384, wl + 4 * 16384,
                                      wh + 5 * 16384, wl + 5 * 16384, b2, t_p, s_p, 0);
    k_mma_gemm<64><<<GB, 256, SM64>>>(noise, wh + 4 * 16384, wl + 4 * 16384,
                                      wh + 5 * 16384, wl + 5 * 16384, nullptr, t_p, s_p, 64);
    k_agg<<<AB, 256>>>(t_p, s_p, out, 1);
}